// round 5
// baseline (speedup 1.0000x reference)
#include <cuda_runtime.h>
#include <cstdint>

#define NB      4
#define GDIM    7
#define NREG    49
#define HH      224
#define CC      256
#define NQ      100
#define ROWS    64      // q rows per CTA (2 q-tiles)
#define THREADS 256     // 8 warps x 8 q-rows
#define KEYS    64      // keys per pass (two 32-key row strips)
#define NPASS   16
#define HSTRIDE (HH*CC) // image pixel-row stride in floats

#define KSTRIDE  260    // sK [KEYS][KSTRIDE]; 260 = 4*65 -> conflict-free lane-strided LDS.128
#define QTSTRIDE 68     // sQt [CC][QTSTRIDE] transposed queries (broadcast reads)
#define PSTRIDE  12     // sP floats per key (48B -> 3k mod 8 bank groups, conflict-free .128)

#define SK_FLOATS  (KEYS*KSTRIDE)        // 16640
#define SQT_FLOATS (CC*QTSTRIDE)         // 17408
#define SP_FLOATS  (8*KEYS*PSTRIDE)      // 6144
#define SMEM_FLOATS (2*SK_FLOATS + SQT_FLOATS + SP_FLOATS)
#define SMEM_BYTES  (SMEM_FLOATS*4)      // 227,328 B

#define OUT_ELEMS (NB*NREG*NQ*CC)
#define POS_ELEMS (NREG*2)

typedef unsigned long long u64;

// ---------------- packed f32x2 helpers ----------------
__device__ __forceinline__ u64 pack2(float a, float b) {
    u64 r; asm("mov.b64 %0, {%1, %2};" : "=l"(r) : "f"(a), "f"(b)); return r;
}
__device__ __forceinline__ void unpack2(u64 v, float& a, float& b) {
    asm("mov.b64 {%0, %1}, %2;" : "=f"(a), "=f"(b) : "l"(v));
}
__device__ __forceinline__ void fma2(u64& d, u64 a, u64 b) {
    asm("fma.rn.f32x2 %0, %1, %2, %0;" : "+l"(d) : "l"(a), "l"(b));
}
__device__ __forceinline__ void mul2(u64& d, u64 a) {
    asm("mul.rn.f32x2 %0, %1, %0;" : "+l"(d) : "l"(a));
}
__device__ __forceinline__ void add2(u64& d, u64 a) {
    asm("add.rn.f32x2 %0, %1, %0;" : "+l"(d) : "l"(a));
}

// ---------------- cp.async helpers ----------------
__device__ __forceinline__ uint32_t s2u(const void* p) {
    return (uint32_t)__cvta_generic_to_shared(p);
}
__device__ __forceinline__ void cp16(uint32_t s, const void* g) {
    asm volatile("cp.async.cg.shared.global [%0], [%1], 16;" :: "r"(s), "l"(g));
}
#define CP_COMMIT() asm volatile("cp.async.commit_group;")
#define CP_WAIT1()  asm volatile("cp.async.wait_group 1;")

// ---------------- fused attention ----------------
// grid: 392 CTAs (196 regions x 2 q-tiles), 256 threads
__global__ void __launch_bounds__(THREADS, 1)
attn_kernel(const float* __restrict__ images,
            const float* __restrict__ queries,
            float* __restrict__ out)
{
    extern __shared__ float smem[];
    float* sK0 = smem;
    float* sK1 = smem + SK_FLOATS;
    float* sQt = smem + 2*SK_FLOATS;
    float* sP  = sQt + SQT_FLOATS;

    const int bx     = blockIdx.x;
    const int region = bx >> 1;
    const int qtile  = bx & 1;
    const int b  = region / NREG;
    const int n  = region % NREG;
    const int gi = n / GDIM;
    const int gj = n % GDIM;

    const int tid  = threadIdx.x;
    const int lane = tid & 31;
    const int warp = tid >> 5;

    const float* imgbase = images + ((size_t)(b*HH + gi*32)*HH + gj*32)*CC;

    // thread-fixed copy geometry: c4 = float col, r0 = base key row
    const int cpc = (tid & 63) * 4;
    const int r0  = tid >> 6;            // 0..3
    const uint32_t sku0 = s2u(sK0);
    const uint32_t sku1 = s2u(sK1);

    // prefetch passes 0 and 1 (16 x 16B per thread each)
    #pragma unroll
    for (int k = 0; k < 16; k++) {
        int r = r0 + 4*k;
        cp16(sku0 + (r*KSTRIDE + cpc)*4,
             imgbase + (size_t)(r >> 5)*HSTRIDE + (r & 31)*CC + cpc);
    }
    CP_COMMIT();
    #pragma unroll
    for (int k = 0; k < 16; k++) {
        int r = r0 + 4*k;
        cp16(sku1 + (r*KSTRIDE + cpc)*4,
             imgbase + (size_t)(2 + (r >> 5))*HSTRIDE + (r & 31)*CC + cpc);
    }
    CP_COMMIT();

    // stage Q transposed: sQt[c][q]  (one-time; conflicts amortized)
    for (int id = tid; id < ROWS*CC; id += THREADS) {
        int q = id >> 8;
        int c = id & 255;
        int qg = qtile*ROWS + q;
        sQt[c*QTSTRIDE + q] = (qg < NQ) ? queries[qg*CC + c] : 0.0f;
    }

    float m[8];
    u64 acc2[4][8];     // acc2[rp][j] = (out[2rp], out[2rp+1]) at channel j
    u64 accl[4];        // row-sum pairs (softmax denominators)
    #pragma unroll
    for (int r = 0; r < 8; r++) m[r] = -1e30f;
    #pragma unroll
    for (int rp = 0; rp < 4; rp++) {
        accl[rp] = 0ull;
        #pragma unroll
        for (int j = 0; j < 8; j++) acc2[rp][j] = 0ull;
    }

    float* sPw = sP + warp*(KEYS*PSTRIDE);
    const float* qb = sQt + warp*8;

    for (int p = 0; p < NPASS; p++) {
        CP_WAIT1();
        __syncthreads();
        const float* sK = (p & 1) ? sK1 : sK0;

        // ---- scores: 8 rows x 64 keys (lane holds keys lane, lane+32) ----
        u64 sa01=0, sa23=0, sa45=0, sa67=0;
        u64 sb01=0, sb23=0, sb45=0, sb67=0;
        const float* kA = sK + lane*KSTRIDE;
        const float* kB = sK + (lane+32)*KSTRIDE;
        #pragma unroll 4
        for (int cb = 0; cb < 64; cb++) {
            float4 ka = *(const float4*)(kA + cb*4);
            float4 kb = *(const float4*)(kB + cb*4);
            #pragma unroll
            for (int cc = 0; cc < 4; cc++) {
                const float* qp = qb + (cb*4 + cc)*QTSTRIDE;
                ulonglong2 q03 = *(const ulonglong2*)qp;        // rows (0,1),(2,3)
                ulonglong2 q47 = *(const ulonglong2*)(qp + 4);  // rows (4,5),(6,7)
                float kaf = cc==0 ? ka.x : cc==1 ? ka.y : cc==2 ? ka.z : ka.w;
                float kbf = cc==0 ? kb.x : cc==1 ? kb.y : cc==2 ? kb.z : kb.w;
                u64 kka = pack2(kaf, kaf);
                u64 kkb = pack2(kbf, kbf);
                fma2(sa01, q03.x, kka); fma2(sa23, q03.y, kka);
                fma2(sa45, q47.x, kka); fma2(sa67, q47.y, kka);
                fma2(sb01, q03.x, kkb); fma2(sb23, q03.y, kkb);
                fma2(sb45, q47.x, kkb); fma2(sb67, q47.y, kkb);
            }
        }
        float sa[8], sb[8];
        unpack2(sa01, sa[0], sa[1]); unpack2(sa23, sa[2], sa[3]);
        unpack2(sa45, sa[4], sa[5]); unpack2(sa67, sa[6], sa[7]);
        unpack2(sb01, sb[0], sb[1]); unpack2(sb23, sb[2], sb[3]);
        unpack2(sb45, sb[4], sb[5]); unpack2(sb67, sb[6], sb[7]);

        // ---- online softmax (max via butterfly; sum folded into PV) ----
        float pa[8], pb[8], al[8];
        #pragma unroll
        for (int r = 0; r < 8; r++) {
            float mx = fmaxf(sa[r], sb[r]);
            #pragma unroll
            for (int o = 16; o; o >>= 1)
                mx = fmaxf(mx, __shfl_xor_sync(0xffffffffu, mx, o));
            float mn = fmaxf(m[r], mx);
            al[r] = __expf(m[r] - mn);
            m[r]  = mn;
            pa[r] = __expf(sa[r] - mn);
            pb[r] = __expf(sb[r] - mn);
        }
        #pragma unroll
        for (int rp = 0; rp < 4; rp++) {
            u64 aa = pack2(al[2*rp], al[2*rp+1]);
            #pragma unroll
            for (int j = 0; j < 8; j++) mul2(acc2[rp][j], aa);
            mul2(accl[rp], aa);
        }

        // ---- publish p to per-warp sP (conflict-free .128) ----
        *(float4*)&sPw[lane*PSTRIDE]          = make_float4(pa[0],pa[1],pa[2],pa[3]);
        *(float4*)&sPw[lane*PSTRIDE + 4]      = make_float4(pa[4],pa[5],pa[6],pa[7]);
        *(float4*)&sPw[(lane+32)*PSTRIDE]     = make_float4(pb[0],pb[1],pb[2],pb[3]);
        *(float4*)&sPw[(lane+32)*PSTRIDE + 4] = make_float4(pb[4],pb[5],pb[6],pb[7]);
        __syncwarp();

        // ---- P*V (+ fold row-sums into accl) ----
        #pragma unroll 2
        for (int s2 = 0; s2 < KEYS; s2++) {
            ulonglong2 p03 = *(const ulonglong2*)&sPw[s2*PSTRIDE];      // (p0,p1),(p2,p3)
            ulonglong2 p47 = *(const ulonglong2*)&sPw[s2*PSTRIDE + 4];  // (p4,p5),(p6,p7)
            float4 v0 = *(const float4*)(sK + s2*KSTRIDE + lane*4);
            float4 v1 = *(const float4*)(sK + s2*KSTRIDE + 128 + lane*4);
            float vf[8] = {v0.x, v0.y, v0.z, v0.w, v1.x, v1.y, v1.z, v1.w};
            #pragma unroll
            for (int j = 0; j < 8; j++) {
                u64 vd = pack2(vf[j], vf[j]);
                fma2(acc2[0][j], p03.x, vd);
                fma2(acc2[1][j], p03.y, vd);
                fma2(acc2[2][j], p47.x, vd);
                fma2(acc2[3][j], p47.y, vd);
            }
            add2(accl[0], p03.x); add2(accl[1], p03.y);
            add2(accl[2], p47.x); add2(accl[3], p47.y);
        }

        __syncthreads();   // all warps done reading sK[p&1]

        // prefetch pass p+2 into the buffer just freed
        if (p + 2 < NPASS) {
            uint32_t sb_ = (p & 1) ? sku1 : sku0;
            const float* gp = imgbase + (size_t)(2*(p+2))*HSTRIDE;
            #pragma unroll
            for (int k = 0; k < 16; k++) {
                int r = r0 + 4*k;
                cp16(sb_ + (r*KSTRIDE + cpc)*4,
                     gp + (size_t)(r >> 5)*HSTRIDE + (r & 31)*CC + cpc);
            }
        }
        CP_COMMIT();
    }

    // ---- epilogue: normalize and store ----
    #pragma unroll
    for (int rp = 0; rp < 4; rp++) {
        float l0, l1;
        unpack2(accl[rp], l0, l1);
        float lo[8], hi[8];
        #pragma unroll
        for (int j = 0; j < 8; j++) unpack2(acc2[rp][j], lo[j], hi[j]);
        int q0 = qtile*ROWS + warp*8 + 2*rp;
        if (q0 < NQ) {
            float inv = 1.0f / l0;
            size_t base = ((size_t)region*NQ + q0)*CC;
            *(float4*)&out[base + lane*4] =
                make_float4(lo[0]*inv, lo[1]*inv, lo[2]*inv, lo[3]*inv);
            *(float4*)&out[base + 128 + lane*4] =
                make_float4(lo[4]*inv, lo[5]*inv, lo[6]*inv, lo[7]*inv);
        }
        if (q0 + 1 < NQ) {
            float inv = 1.0f / l1;
            size_t base = ((size_t)region*NQ + q0 + 1)*CC;
            *(float4*)&out[base + lane*4] =
                make_float4(hi[0]*inv, hi[1]*inv, hi[2]*inv, hi[3]*inv);
            *(float4*)&out[base + 128 + lane*4] =
                make_float4(hi[4]*inv, hi[5]*inv, hi[6]*inv, hi[7]*inv);
        }
    }
}

// ---------------- positions (second tuple output) ----------------
__global__ void pos_kernel(float* __restrict__ out, int out_size) {
    int t = threadIdx.x;
    if (t < NREG && out_size >= OUT_ELEMS + POS_ELEMS) {
        out[OUT_ELEMS + 2*t + 0] = (float)(t / GDIM) * (1.0f / 7.0f);
        out[OUT_ELEMS + 2*t + 1] = (float)(t % GDIM) * (1.0f / 7.0f);
    }
}

extern "C" void kernel_launch(void* const* d_in, const int* in_sizes, int n_in,
                              void* d_out, int out_size) {
    const float* images  = (const float*)d_in[0];
    const float* queries = (const float*)d_in[1];
    if (n_in >= 2 && in_sizes[0] == NQ*CC) {
        const float* t = images; images = queries; queries = t;
    }
    float* out = (float*)d_out;

    cudaFuncSetAttribute(attn_kernel,
                         cudaFuncAttributeMaxDynamicSharedMemorySize, SMEM_BYTES);

    // pos_kernel first so ncu "-s 5 -c 1" lands on attn_kernel
    pos_kernel<<<1, 64>>>(out, out_size);
    attn_kernel<<<196*2, THREADS, SMEM_BYTES>>>(images, queries, out);
}

// round 6
// speedup vs baseline: 1.0024x; 1.0024x over previous
#include <cuda_runtime.h>
#include <cstdint>

#define NB      4
#define GDIM    7
#define NREG    49
#define HH      224
#define CC      256
#define NQ      100
#define ROWS    64      // q rows per CTA (2 q-tiles)
#define THREADS 256     // 8 warps x 8 q-rows
#define KEYS    64      // keys per pass (two 32-key row strips)
#define NPASS   16
#define HSTRIDE (HH*CC) // image pixel-row stride in floats

#define KSTRIDE  260    // sK [KEYS][KSTRIDE]; 260 = 4*65 -> conflict-free lane-strided LDS.128
#define QTSTRIDE 68     // sQt [CC][QTSTRIDE] transposed queries (broadcast reads)
#define PSTRIDE  12     // sP floats per key (48B -> 3k mod 8 bank groups, conflict-free .128)

#define SK_FLOATS  (KEYS*KSTRIDE)        // 16640
#define SQT_FLOATS (CC*QTSTRIDE)         // 17408
#define SP_FLOATS  (8*KEYS*PSTRIDE)      // 6144
#define SMEM_FLOATS (2*SK_FLOATS + SQT_FLOATS + SP_FLOATS)
#define SMEM_BYTES  (SMEM_FLOATS*4)      // 227,328 B

#define OUT_ELEMS (NB*NREG*NQ*CC)
#define POS_ELEMS (NREG*2)

typedef unsigned long long u64;

// ---------------- packed f32x2 helpers ----------------
__device__ __forceinline__ u64 pack2(float a, float b) {
    u64 r; asm("mov.b64 %0, {%1, %2};" : "=l"(r) : "f"(a), "f"(b)); return r;
}
__device__ __forceinline__ void unpack2(u64 v, float& a, float& b) {
    asm("mov.b64 {%0, %1}, %2;" : "=f"(a), "=f"(b) : "l"(v));
}
__device__ __forceinline__ void fma2(u64& d, u64 a, u64 b) {
    asm("fma.rn.f32x2 %0, %1, %2, %0;" : "+l"(d) : "l"(a), "l"(b));
}
__device__ __forceinline__ void mul2(u64& d, u64 a) {
    asm("mul.rn.f32x2 %0, %1, %0;" : "+l"(d) : "l"(a));
}
__device__ __forceinline__ void add2(u64& d, u64 a) {
    asm("add.rn.f32x2 %0, %1, %0;" : "+l"(d) : "l"(a));
}

// ---------------- cp.async helpers ----------------
__device__ __forceinline__ uint32_t s2u(const void* p) {
    return (uint32_t)__cvta_generic_to_shared(p);
}
__device__ __forceinline__ void cp16(uint32_t s, const void* g) {
    asm volatile("cp.async.cg.shared.global [%0], [%1], 16;" :: "r"(s), "l"(g));
}
#define CP_COMMIT() asm volatile("cp.async.commit_group;")
#define CP_WAIT1()  asm volatile("cp.async.wait_group 1;")

// ---------------- fused attention ----------------
// grid: 392 CTAs (196 regions x 2 q-tiles), 256 threads
__global__ void __launch_bounds__(THREADS, 1)
attn_kernel(const float* __restrict__ images,
            const float* __restrict__ queries,
            float* __restrict__ out)
{
    extern __shared__ float smem[];
    float* sK0 = smem;
    float* sK1 = smem + SK_FLOATS;
    float* sQt = smem + 2*SK_FLOATS;
    float* sP  = sQt + SQT_FLOATS;

    const int bx     = blockIdx.x;
    const int region = bx >> 1;
    const int qtile  = bx & 1;
    const int b  = region / NREG;
    const int n  = region % NREG;
    const int gi = n / GDIM;
    const int gj = n % GDIM;

    const int tid  = threadIdx.x;
    const int lane = tid & 31;
    const int warp = tid >> 5;

    const float* imgbase = images + ((size_t)(b*HH + gi*32)*HH + gj*32)*CC;

    // thread-fixed copy geometry: c4 = float col, r0 = base key row
    const int cpc = (tid & 63) * 4;
    const int r0  = tid >> 6;            // 0..3
    const uint32_t sku0 = s2u(sK0);
    const uint32_t sku1 = s2u(sK1);

    // prefetch passes 0 and 1 (16 x 16B per thread each)
    #pragma unroll
    for (int k = 0; k < 16; k++) {
        int r = r0 + 4*k;
        cp16(sku0 + (r*KSTRIDE + cpc)*4,
             imgbase + (size_t)(r >> 5)*HSTRIDE + (r & 31)*CC + cpc);
    }
    CP_COMMIT();
    #pragma unroll
    for (int k = 0; k < 16; k++) {
        int r = r0 + 4*k;
        cp16(sku1 + (r*KSTRIDE + cpc)*4,
             imgbase + (size_t)(2 + (r >> 5))*HSTRIDE + (r & 31)*CC + cpc);
    }
    CP_COMMIT();

    // stage Q transposed: sQt[c][q]  (one-time; conflicts amortized)
    for (int id = tid; id < ROWS*CC; id += THREADS) {
        int q = id >> 8;
        int c = id & 255;
        int qg = qtile*ROWS + q;
        sQt[c*QTSTRIDE + q] = (qg < NQ) ? queries[qg*CC + c] : 0.0f;
    }

    float m[8];
    u64 acc2[4][8];     // acc2[rp][j] = (out[2rp], out[2rp+1]) at channel j
    u64 accl[4];        // row-sum pairs (softmax denominators)
    #pragma unroll
    for (int r = 0; r < 8; r++) m[r] = -1e30f;
    #pragma unroll
    for (int rp = 0; rp < 4; rp++) {
        accl[rp] = 0ull;
        #pragma unroll
        for (int j = 0; j < 8; j++) acc2[rp][j] = 0ull;
    }

    float* sPw = sP + warp*(KEYS*PSTRIDE);
    const float* qb = sQt + warp*8;

    for (int p = 0; p < NPASS; p++) {
        CP_WAIT1();
        __syncthreads();
        const float* sK = (p & 1) ? sK1 : sK0;

        // ---- scores: 8 rows x 64 keys (lane holds keys lane, lane+32) ----
        u64 sa01=0, sa23=0, sa45=0, sa67=0;
        u64 sb01=0, sb23=0, sb45=0, sb67=0;
        const float* kA = sK + lane*KSTRIDE;
        const float* kB = sK + (lane+32)*KSTRIDE;
        #pragma unroll 4
        for (int cb = 0; cb < 64; cb++) {
            float4 ka = *(const float4*)(kA + cb*4);
            float4 kb = *(const float4*)(kB + cb*4);
            #pragma unroll
            for (int cc = 0; cc < 4; cc++) {
                const float* qp = qb + (cb*4 + cc)*QTSTRIDE;
                ulonglong2 q03 = *(const ulonglong2*)qp;        // rows (0,1),(2,3)
                ulonglong2 q47 = *(const ulonglong2*)(qp + 4);  // rows (4,5),(6,7)
                float kaf = cc==0 ? ka.x : cc==1 ? ka.y : cc==2 ? ka.z : ka.w;
                float kbf = cc==0 ? kb.x : cc==1 ? kb.y : cc==2 ? kb.z : kb.w;
                u64 kka = pack2(kaf, kaf);
                u64 kkb = pack2(kbf, kbf);
                fma2(sa01, q03.x, kka); fma2(sa23, q03.y, kka);
                fma2(sa45, q47.x, kka); fma2(sa67, q47.y, kka);
                fma2(sb01, q03.x, kkb); fma2(sb23, q03.y, kkb);
                fma2(sb45, q47.x, kkb); fma2(sb67, q47.y, kkb);
            }
        }
        float sa[8], sb[8];
        unpack2(sa01, sa[0], sa[1]); unpack2(sa23, sa[2], sa[3]);
        unpack2(sa45, sa[4], sa[5]); unpack2(sa67, sa[6], sa[7]);
        unpack2(sb01, sb[0], sb[1]); unpack2(sb23, sb[2], sb[3]);
        unpack2(sb45, sb[4], sb[5]); unpack2(sb67, sb[6], sb[7]);

        // ---- online softmax (max via butterfly; sum folded into PV) ----
        float pa[8], pb[8], al[8];
        #pragma unroll
        for (int r = 0; r < 8; r++) {
            float mx = fmaxf(sa[r], sb[r]);
            #pragma unroll
            for (int o = 16; o; o >>= 1)
                mx = fmaxf(mx, __shfl_xor_sync(0xffffffffu, mx, o));
            float mn = fmaxf(m[r], mx);
            al[r] = __expf(m[r] - mn);
            m[r]  = mn;
            pa[r] = __expf(sa[r] - mn);
            pb[r] = __expf(sb[r] - mn);
        }
        #pragma unroll
        for (int rp = 0; rp < 4; rp++) {
            u64 aa = pack2(al[2*rp], al[2*rp+1]);
            #pragma unroll
            for (int j = 0; j < 8; j++) mul2(acc2[rp][j], aa);
            mul2(accl[rp], aa);
        }

        // ---- publish p to per-warp sP (conflict-free .128) ----
        *(float4*)&sPw[lane*PSTRIDE]          = make_float4(pa[0],pa[1],pa[2],pa[3]);
        *(float4*)&sPw[lane*PSTRIDE + 4]      = make_float4(pa[4],pa[5],pa[6],pa[7]);
        *(float4*)&sPw[(lane+32)*PSTRIDE]     = make_float4(pb[0],pb[1],pb[2],pb[3]);
        *(float4*)&sPw[(lane+32)*PSTRIDE + 4] = make_float4(pb[4],pb[5],pb[6],pb[7]);
        __syncwarp();

        // ---- P*V (+ fold row-sums into accl) ----
        #pragma unroll 2
        for (int s2 = 0; s2 < KEYS; s2++) {
            ulonglong2 p03 = *(const ulonglong2*)&sPw[s2*PSTRIDE];      // (p0,p1),(p2,p3)
            ulonglong2 p47 = *(const ulonglong2*)&sPw[s2*PSTRIDE + 4];  // (p4,p5),(p6,p7)
            float4 v0 = *(const float4*)(sK + s2*KSTRIDE + lane*4);
            float4 v1 = *(const float4*)(sK + s2*KSTRIDE + 128 + lane*4);
            float vf[8] = {v0.x, v0.y, v0.z, v0.w, v1.x, v1.y, v1.z, v1.w};
            #pragma unroll
            for (int j = 0; j < 8; j++) {
                u64 vd = pack2(vf[j], vf[j]);
                fma2(acc2[0][j], p03.x, vd);
                fma2(acc2[1][j], p03.y, vd);
                fma2(acc2[2][j], p47.x, vd);
                fma2(acc2[3][j], p47.y, vd);
            }
            add2(accl[0], p03.x); add2(accl[1], p03.y);
            add2(accl[2], p47.x); add2(accl[3], p47.y);
        }

        __syncthreads();   // all warps done reading sK[p&1]

        // prefetch pass p+2 into the buffer just freed
        if (p + 2 < NPASS) {
            uint32_t sb_ = (p & 1) ? sku1 : sku0;
            const float* gp = imgbase + (size_t)(2*(p+2))*HSTRIDE;
            #pragma unroll
            for (int k = 0; k < 16; k++) {
                int r = r0 + 4*k;
                cp16(sb_ + (r*KSTRIDE + cpc)*4,
                     gp + (size_t)(r >> 5)*HSTRIDE + (r & 31)*CC + cpc);
            }
        }
        CP_COMMIT();
    }

    // ---- epilogue: normalize and store ----
    #pragma unroll
    for (int rp = 0; rp < 4; rp++) {
        float l0, l1;
        unpack2(accl[rp], l0, l1);
        float lo[8], hi[8];
        #pragma unroll
        for (int j = 0; j < 8; j++) unpack2(acc2[rp][j], lo[j], hi[j]);
        int q0 = qtile*ROWS + warp*8 + 2*rp;
        if (q0 < NQ) {
            float inv = 1.0f / l0;
            size_t base = ((size_t)region*NQ + q0)*CC;
            *(float4*)&out[base + lane*4] =
                make_float4(lo[0]*inv, lo[1]*inv, lo[2]*inv, lo[3]*inv);
            *(float4*)&out[base + 128 + lane*4] =
                make_float4(lo[4]*inv, lo[5]*inv, lo[6]*inv, lo[7]*inv);
        }
        if (q0 + 1 < NQ) {
            float inv = 1.0f / l1;
            size_t base = ((size_t)region*NQ + q0 + 1)*CC;
            *(float4*)&out[base + lane*4] =
                make_float4(hi[0]*inv, hi[1]*inv, hi[2]*inv, hi[3]*inv);
            *(float4*)&out[base + 128 + lane*4] =
                make_float4(hi[4]*inv, hi[5]*inv, hi[6]*inv, hi[7]*inv);
        }
    }
}

// ---------------- positions (second tuple output) ----------------
__global__ void pos_kernel(float* __restrict__ out, int out_size) {
    int t = threadIdx.x;
    if (t < NREG && out_size >= OUT_ELEMS + POS_ELEMS) {
        out[OUT_ELEMS + 2*t + 0] = (float)(t / GDIM) * (1.0f / 7.0f);
        out[OUT_ELEMS + 2*t + 1] = (float)(t % GDIM) * (1.0f / 7.0f);
    }
}

extern "C" void kernel_launch(void* const* d_in, const int* in_sizes, int n_in,
                              void* d_out, int out_size) {
    const float* images  = (const float*)d_in[0];
    const float* queries = (const float*)d_in[1];
    if (n_in >= 2 && in_sizes[0] == NQ*CC) {
        const float* t = images; images = queries; queries = t;
    }
    float* out = (float*)d_out;

    cudaFuncSetAttribute(attn_kernel,
                         cudaFuncAttributeMaxDynamicSharedMemorySize, SMEM_BYTES);

    // pos_kernel first so ncu "-s 5 -c 1" lands on attn_kernel
    pos_kernel<<<1, 64>>>(out, out_size);
    attn_kernel<<<196*2, THREADS, SMEM_BYTES>>>(images, queries, out);
}